// round 16
// baseline (speedup 1.0000x reference)
#include <cuda_runtime.h>
#include <cstdint>

#define DDEPTH 8
#define HDIM   4096
#define NT     512
#define NWARP  (NT / 32)    // 16
#define HPT    8            // hidden dims per thread (512*8 = 4096)
#define EPSV   1e-6f
#define STAGES 3            // TMA ring, pair-granular stages
#define ROW_BYTES  (HDIM * 4)        // one depth row of one site: 16 KiB
#define PAIR_BYTES (2 * ROW_BYTES)   // 32 KiB

#define DOT4(a,b) ((a).x*(b).x + (a).y*(b).y + (a).z*(b).z + (a).w*(b).w)

__device__ __forceinline__ uint32_t smem_u32(const void* p) {
    uint32_t a;
    asm("{ .reg .u64 t; cvta.to.shared.u64 t, %1; cvt.u32.u64 %0, t; }"
        : "=r"(a) : "l"(p));
    return a;
}
__device__ __forceinline__ void mbar_init(uint32_t mb, uint32_t cnt) {
    asm volatile("mbarrier.init.shared.b64 [%0], %1;" :: "r"(mb), "r"(cnt) : "memory");
}
__device__ __forceinline__ void mbar_expect_tx(uint32_t mb, uint32_t bytes) {
    asm volatile("mbarrier.arrive.expect_tx.shared.b64 _, [%0], %1;"
                 :: "r"(mb), "r"(bytes) : "memory");
}
__device__ __forceinline__ void mbar_arrive(uint32_t mb) {
    asm volatile("mbarrier.arrive.shared.b64 _, [%0];" :: "r"(mb) : "memory");
}
__device__ __forceinline__ void mbar_wait(uint32_t mb, uint32_t parity) {
    uint32_t done;
    asm volatile(
        "{ .reg .pred p;"
        "  mbarrier.try_wait.parity.acquire.cta.shared::cta.b64 p, [%1], %2;"
        "  selp.b32 %0, 1, 0, p; }"
        : "=r"(done) : "r"(mb), "r"(parity) : "memory");
    if (!done) {
        asm volatile(
            "{ .reg .pred P1;"
            "WAIT_LOOP_%=:"
            "  mbarrier.try_wait.parity.acquire.cta.shared::cta.b64 P1, [%0], %1, 0x989680;"
            "  @P1 bra.uni WAIT_DONE_%=;"
            "  bra.uni WAIT_LOOP_%=;"
            "WAIT_DONE_%=: }"
            :: "r"(mb), "r"(parity) : "memory");
    }
}
__device__ __forceinline__ void bulk_cp(uint32_t sdst, const float* gsrc,
                                        uint32_t bytes, uint32_t mb) {
    asm volatile(
        "cp.async.bulk.shared::cluster.global.mbarrier::complete_tx::bytes "
        "[%0], [%1], %2, [%3];"
        :: "r"(sdst), "l"(gsrc), "r"(bytes), "r"(mb) : "memory");
}

// Persistent CTAs (2/SM). TMA bulk ring (pair stages) -> QUAD reduction rounds:
// 4 depths per round, 2 rounds/site. Halves barriers/scans/softmax chains per
// site vs the pair version; smem ring means no prefetch register cost.
__global__ __launch_bounds__(NT, 2)
void fullattnres_kernel(const float* __restrict__ values,
                        const float* __restrict__ query,
                        const float* __restrict__ weight,
                        float* __restrict__ out,
                        int SB)
{
    extern __shared__ float sbuf[];      // [STAGES][2][HDIM] floats (96 KiB)
    __shared__ float4 redSS[2][NWARP];   // {ss0..ss3} per warp, parity buffered
    __shared__ float4 redDP[2][NWARP];   // {dp0..dp3} per warp
    __shared__ unsigned long long full_b[STAGES], empty_b[STAGES];

    const int tid  = threadIdx.x;
    const int lane = tid & 31;
    const int warp = tid >> 5;
    const int h    = tid * HPT;
    const int grid = gridDim.x;
    const size_t dstr = (size_t)SB * HDIM;

    if ((int)blockIdx.x >= SB) return;
    const int nsites = (SB - 1 - (int)blockIdx.x) / grid + 1;
    const int npairs = nsites * 4;

    uint32_t full_a[STAGES], empty_a[STAGES];
    #pragma unroll
    for (int i = 0; i < STAGES; i++) {
        full_a[i]  = smem_u32(&full_b[i]);
        empty_a[i] = smem_u32(&empty_b[i]);
    }
    if (tid == 0) {
        #pragma unroll
        for (int i = 0; i < STAGES; i++) { mbar_init(full_a[i], 1); mbar_init(empty_a[i], 1); }
    }
    __syncthreads();

    // fused q*w, loaded ONCE per CTA
    const float4 q0 = *(const float4*)(query + h);
    const float4 q1 = *(const float4*)(query + h + 4);
    const float4 w0 = *(const float4*)(weight + h);
    const float4 w1 = *(const float4*)(weight + h + 4);
    const float4 qw0 = make_float4(q0.x*w0.x, q0.y*w0.y, q0.z*w0.z, q0.w*w0.w);
    const float4 qw1 = make_float4(q1.x*w1.x, q1.y*w1.y, q1.z*w1.z, q1.w*w1.w);

    const uint32_t sbase = smem_u32(sbuf);

    int p_stage = 0, p_phase = 1;   // producer cursor (tid0)
    int c_stage = 0, c_phase = 0;   // consumer cursor (pair granular)
    int next_g  = 0;                // next pair index to issue

    auto issue_pair = [&](int g) {   // tid==0 only
        mbar_wait(empty_a[p_stage], (uint32_t)p_phase);
        const int psite = (int)blockIdx.x + (g >> 2) * grid;
        const int ppr   = g & 3;
        const float* gb = values + (size_t)psite * HDIM + (size_t)(2 * ppr) * dstr;
        const uint32_t sd = sbase + (uint32_t)p_stage * PAIR_BYTES;
        mbar_expect_tx(full_a[p_stage], PAIR_BYTES);
        bulk_cp(sd,             gb,        ROW_BYTES, full_a[p_stage]);
        bulk_cp(sd + ROW_BYTES, gb + dstr, ROW_BYTES, full_a[p_stage]);
        if (++p_stage == STAGES) { p_stage = 0; p_phase ^= 1; }
    };

    // prologue: fill the whole ring (3 pairs in flight)
    if (tid == 0) { issue_pair(0); issue_pair(1); issue_pair(2); next_g = 3; }

    int parity = 0;

    for (int si = 0; si < nsites; si++) {
        const int site = (int)blockIdx.x + si * grid;

        float  m = -3.402823466e38f;
        float  s = 0.f;
        float4 acc0 = make_float4(0.f, 0.f, 0.f, 0.f);
        float4 acc1 = make_float4(0.f, 0.f, 0.f, 0.f);

        #pragma unroll
        for (int r = 0; r < 2; r++) {        // 2 quad-rounds per site
            // cursors for the two pairs of this quad
            const int s0 = c_stage, ph0 = c_phase;
            if (++c_stage == STAGES) { c_stage = 0; c_phase ^= 1; }
            const int s1 = c_stage, ph1 = c_phase;
            if (++c_stage == STAGES) { c_stage = 0; c_phase ^= 1; }

            mbar_wait(full_a[s0], (uint32_t)ph0);
            mbar_wait(full_a[s1], (uint32_t)ph1);

            // read 4 depths: pair A from stage s0, pair B from stage s1
            const float* cb0 = sbuf + s0 * 2 * HDIM + h;
            const float* cb1 = sbuf + s1 * 2 * HDIM + h;
            const float4 va0 = *(const float4*)(cb0);
            const float4 va1 = *(const float4*)(cb0 + 4);
            const float4 vb0 = *(const float4*)(cb0 + HDIM);
            const float4 vb1 = *(const float4*)(cb0 + HDIM + 4);
            const float4 vc0 = *(const float4*)(cb1);
            const float4 vc1 = *(const float4*)(cb1 + 4);
            const float4 vd0 = *(const float4*)(cb1 + HDIM);
            const float4 vd1 = *(const float4*)(cb1 + HDIM + 4);

            // 8 partial scalars
            float ss0 = DOT4(va0, va0) + DOT4(va1, va1);
            float ss1 = DOT4(vb0, vb0) + DOT4(vb1, vb1);
            float ss2 = DOT4(vc0, vc0) + DOT4(vc1, vc1);
            float ss3 = DOT4(vd0, vd0) + DOT4(vd1, vd1);
            float dp0 = DOT4(qw0, va0) + DOT4(qw1, va1);
            float dp1 = DOT4(qw0, vb0) + DOT4(qw1, vb1);
            float dp2 = DOT4(qw0, vc0) + DOT4(qw1, vc1);
            float dp3 = DOT4(qw0, vd0) + DOT4(qw1, vd1);

            // one 5-round butterfly over 8 independent scalars
            #pragma unroll
            for (int off = 16; off > 0; off >>= 1) {
                ss0 += __shfl_xor_sync(0xFFFFFFFFu, ss0, off);
                ss1 += __shfl_xor_sync(0xFFFFFFFFu, ss1, off);
                ss2 += __shfl_xor_sync(0xFFFFFFFFu, ss2, off);
                ss3 += __shfl_xor_sync(0xFFFFFFFFu, ss3, off);
                dp0 += __shfl_xor_sync(0xFFFFFFFFu, dp0, off);
                dp1 += __shfl_xor_sync(0xFFFFFFFFu, dp1, off);
                dp2 += __shfl_xor_sync(0xFFFFFFFFu, dp2, off);
                dp3 += __shfl_xor_sync(0xFFFFFFFFu, dp3, off);
            }
            if (lane == 0) {
                redSS[parity][warp] = make_float4(ss0, ss1, ss2, ss3);
                redDP[parity][warp] = make_float4(dp0, dp1, dp2, dp3);
            }
            __syncthreads();   // ONE barrier per quad; also proves LDS reads done

            // free both consumed stages, then refill the ring (TMA engine works
            // through the rest of the tail + next round's compute)
            if (tid == 0) {
                mbar_arrive(empty_a[s0]);
                mbar_arrive(empty_a[s1]);
                if (next_g < npairs) issue_pair(next_g++);
                if (next_g < npairs) issue_pair(next_g++);
            }

            // distributed scan: 2 LDS.128 + two 4-round f4 butterflies
            float4 tS = redSS[parity][lane & 15];
            float4 tD = redDP[parity][lane & 15];
            #pragma unroll
            for (int off = 8; off > 0; off >>= 1) {
                tS.x += __shfl_xor_sync(0xFFFFFFFFu, tS.x, off);
                tS.y += __shfl_xor_sync(0xFFFFFFFFu, tS.y, off);
                tS.z += __shfl_xor_sync(0xFFFFFFFFu, tS.z, off);
                tS.w += __shfl_xor_sync(0xFFFFFFFFu, tS.w, off);
                tD.x += __shfl_xor_sync(0xFFFFFFFFu, tD.x, off);
                tD.y += __shfl_xor_sync(0xFFFFFFFFu, tD.y, off);
                tD.z += __shfl_xor_sync(0xFFFFFFFFu, tD.z, off);
                tD.w += __shfl_xor_sync(0xFFFFFFFFu, tD.w, off);
            }
            parity ^= 1;

            const float l0 = tD.x * rsqrtf(tS.x * (1.0f / HDIM) + EPSV);
            const float l1 = tD.y * rsqrtf(tS.y * (1.0f / HDIM) + EPSV);
            const float l2 = tD.z * rsqrtf(tS.z * (1.0f / HDIM) + EPSV);
            const float l3 = tD.w * rsqrtf(tS.w * (1.0f / HDIM) + EPSV);

            // joint online-softmax update over 4 depths
            const float mn = fmaxf(fmaxf(m, fmaxf(l0, l1)), fmaxf(l2, l3));
            const float cs = __expf(m - mn);     // first round: exp(-inf)=0
            const float e0 = __expf(l0 - mn);
            const float e1 = __expf(l1 - mn);
            const float e2 = __expf(l2 - mn);
            const float e3 = __expf(l3 - mn);
            s = s * cs + e0 + e1 + e2 + e3;
            acc0.x = acc0.x*cs + e0*va0.x + e1*vb0.x + e2*vc0.x + e3*vd0.x;
            acc0.y = acc0.y*cs + e0*va0.y + e1*vb0.y + e2*vc0.y + e3*vd0.y;
            acc0.z = acc0.z*cs + e0*va0.z + e1*vb0.z + e2*vc0.z + e3*vd0.z;
            acc0.w = acc0.w*cs + e0*va0.w + e1*vb0.w + e2*vc0.w + e3*vd0.w;
            acc1.x = acc1.x*cs + e0*va1.x + e1*vb1.x + e2*vc1.x + e3*vd1.x;
            acc1.y = acc1.y*cs + e0*va1.y + e1*vb1.y + e2*vc1.y + e3*vd1.y;
            acc1.z = acc1.z*cs + e0*va1.z + e1*vb1.z + e2*vc1.z + e3*vd1.z;
            acc1.w = acc1.w*cs + e0*va1.w + e1*vb1.w + e2*vc1.w + e3*vd1.w;
            m = mn;
        }

        // finalize + store this site
        const float inv = 1.0f / s;
        const size_t ob = (size_t)site * HDIM + h;
        *(float4*)(out + ob)     = make_float4(acc0.x*inv, acc0.y*inv, acc0.z*inv, acc0.w*inv);
        *(float4*)(out + ob + 4) = make_float4(acc1.x*inv, acc1.y*inv, acc1.z*inv, acc1.w*inv);
    }
}

extern "C" void kernel_launch(void* const* d_in, const int* in_sizes, int n_in,
                              void* d_out, int out_size)
{
    const float* values = (const float*)d_in[0];  // [D,S,B,H]
    const float* query  = (const float*)d_in[1];  // [H]
    const float* weight = (const float*)d_in[2];  // [H]
    float* out = (float*)d_out;                   // [S,B,H]

    const int H  = in_sizes[1];                   // 4096
    const int SB = out_size / H;                  // S*B = 4096

    const size_t smem_bytes = (size_t)STAGES * PAIR_BYTES;  // 96 KiB
    cudaFuncSetAttribute(fullattnres_kernel,
                         cudaFuncAttributeMaxDynamicSharedMemorySize,
                         (int)smem_bytes);

    int sms = 148;
    cudaDeviceGetAttribute(&sms, cudaDevAttrMultiProcessorCount, 0);
    int grid = 2 * sms;                           // persistent: 2 CTAs per SM
    if (grid > SB) grid = SB;

    fullattnres_kernel<<<grid, NT, smem_bytes>>>(values, query, weight, out, SB);
}